// round 2
// baseline (speedup 1.0000x reference)
#include <cuda_runtime.h>
#include <cuda_bf16.h>
#include <cstdint>
#include <cstddef>

#define BATCH    8
#define NPTS     8192
#define NPOINT_  1024
#define NSAMPLE_ 32
#define CFEAT    64

// scratch (device globals; no allocation allowed)
__device__ int   g_gidx[BATCH * NPOINT_ * NSAMPLE_];   // ball-query neighbor indices
__device__ float g_featproj[BATCH * NPTS * CFEAT];     // W1[:,3:] @ features per unique point

// ---------------------------------------------------------------------------
// Kernel 1: farthest point sampling. One CTA per batch, 512 thr x 16 pts in regs.
// Writes new_xyz (B,1024,3) to the front of d_out.
// ---------------------------------------------------------------------------
__global__ void __launch_bounds__(512, 1) fps_kernel(const float* __restrict__ xyz,
                                                     float* __restrict__ newxyz)
{
    __shared__ unsigned long long skey[32];   // double-buffered warp partials (16 warps)

    const int b = blockIdx.x;
    const int t = threadIdx.x;
    const float* xb = xyz + (size_t)b * NPTS * 3;

    float px[16], py[16], pz[16], pd[16];
#pragma unroll
    for (int j = 0; j < 16; ++j) {
        int i = t + j * 512;
        px[j] = xb[i * 3 + 0];
        py[j] = xb[i * 3 + 1];
        pz[j] = xb[i * 3 + 2];
        pd[j] = 1e10f;
    }

    float lx = xb[0], ly = xb[1], lz = xb[2];
    if (t == 0) {
        newxyz[(b * NPOINT_) * 3 + 0] = lx;
        newxyz[(b * NPOINT_) * 3 + 1] = ly;
        newxyz[(b * NPOINT_) * 3 + 2] = lz;
    }

    const int lane = t & 31, wid = t >> 5;

    for (int it = 1; it < NPOINT_; ++it) {
        float best = -1.0f;
        int bi = 0;
#pragma unroll
        for (int j = 0; j < 16; ++j) {
            float dx = px[j] - lx, dy = py[j] - ly, dz = pz[j] - lz;
            float d = fmaf(dx, dx, fmaf(dy, dy, dz * dz));
            d = fminf(pd[j], d);
            pd[j] = d;
            if (d > best) { best = d; bi = j; }
        }
        // key: max dist; tie -> min index (jnp.argmax first-occurrence semantics)
        unsigned long long key = ((unsigned long long)__float_as_uint(best) << 32)
                               | (unsigned)(8191 - (t + bi * 512));
#pragma unroll
        for (int s = 16; s > 0; s >>= 1) {
            unsigned long long o = __shfl_xor_sync(0xffffffffu, key, s);
            key = (o > key) ? o : key;
        }
        const int off = (it & 1) * 16;
        if (lane == 0) skey[off + wid] = key;
        __syncthreads();
        unsigned long long k2 = skey[off + (lane & 15)];
#pragma unroll
        for (int s = 8; s > 0; s >>= 1) {
            unsigned long long o = __shfl_xor_sync(0xffffffffu, k2, s);
            k2 = (o > k2) ? o : k2;
        }
        const int win = 8191 - (int)(unsigned)(k2 & 0xffffffffull);
        lx = xb[win * 3 + 0];
        ly = xb[win * 3 + 1];
        lz = xb[win * 3 + 2];
        if (t == 0) {
            newxyz[(b * NPOINT_ + it) * 3 + 0] = lx;
            newxyz[(b * NPOINT_ + it) * 3 + 1] = ly;
            newxyz[(b * NPOINT_ + it) * 3 + 2] = lz;
        }
    }
}

// ---------------------------------------------------------------------------
// Kernel 2: layer-1 feature projection for all unique points.
// g_featproj[b,n,o] = sum_c w1[o][3+c] * feat[b,n,c]   (no bias, no relu yet)
// One warp per point row; lane handles out-channels {lane, lane+32}.
// ---------------------------------------------------------------------------
__global__ void __launch_bounds__(256) featproj_kernel(const float* __restrict__ feat,
                                                       const float* __restrict__ w1)
{
    __shared__ float ws[64 * 65];   // [o][c], padded stride to avoid conflicts
    __shared__ float sf[8][64];

    const int tid = threadIdx.x;
    for (int i = tid; i < 64 * 64; i += 256) {
        int o = i >> 6, c = i & 63;
        ws[o * 65 + c] = w1[o * 67 + 3 + c];
    }
    __syncthreads();

    const int wid = tid >> 5, lane = tid & 31;
    const int row = blockIdx.x * 8 + wid;              // 65536 rows
    const float* fr = feat + (size_t)row * 64;
    sf[wid][lane]      = fr[lane];
    sf[wid][lane + 32] = fr[lane + 32];
    __syncwarp();

    float a0 = 0.f, a1 = 0.f;
#pragma unroll
    for (int c = 0; c < 64; ++c) {
        float f = sf[wid][c];
        a0 = fmaf(ws[lane * 65 + c],        f, a0);
        a1 = fmaf(ws[(lane + 32) * 65 + c], f, a1);
    }
    float* outr = g_featproj + (size_t)row * 64;
    outr[lane]      = a0;
    outr[lane + 32] = a1;
}

// ---------------------------------------------------------------------------
// Kernel 3: ball query. One warp per center; first-32-by-index, pad with first.
// ---------------------------------------------------------------------------
__global__ void __launch_bounds__(256) ballquery_kernel(const float* __restrict__ xyz,
                                                        const float* __restrict__ newxyz)
{
    const int gw = (blockIdx.x * blockDim.x + threadIdx.x) >> 5;  // center id (8192)
    const int lane = threadIdx.x & 31;
    const int b = gw >> 10;
    const float* xb = xyz + (size_t)b * NPTS * 3;
    const float cx = newxyz[gw * 3 + 0];
    const float cy = newxyz[gw * 3 + 1];
    const float cz = newxyz[gw * 3 + 2];
    int* out = g_gidx + gw * 32;

    const float R2 = (float)(0.4 * 0.4);
    int cnt = 0, first = 0;
    bool hasfirst = false;
    for (int p0 = 0; p0 < NPTS && cnt < 32; p0 += 32) {
        int p = p0 + lane;
        float dx = xb[p * 3 + 0] - cx;
        float dy = xb[p * 3 + 1] - cy;
        float dz = xb[p * 3 + 2] - cz;
        float d2 = fmaf(dx, dx, fmaf(dy, dy, dz * dz));
        bool in = d2 < R2;
        unsigned mask = __ballot_sync(0xffffffffu, in);
        if (mask) {
            if (!hasfirst) { first = p0 + __ffs(mask) - 1; hasfirst = true; }
            int ofs = cnt + __popc(mask & ((1u << lane) - 1u));
            if (in && ofs < 32) out[ofs] = p;
            cnt += __popc(mask);
        }
    }
    for (int s = cnt + lane; s < 32; s += 32) out[s] = first;
}

// ---------------------------------------------------------------------------
// Kernel 4: fused gather + 3-layer MLP + max-pool. Warp per center, lane = sample.
// Dynamic smem layout (floats):
//   [0,256)       w1p: float4(w1x, w1y, w1z, b1) per out-channel (64 x 4)
//   [256,320)     b2
//   [320,448)     b3
//   [448,4544)    w2t  [c 64][o 64]
//   [4544,12736)  w3t  [c 64][o 128]
//   [12736,13248) sout [o 128][warp 4]  (transpose for coalesced store)
// ---------------------------------------------------------------------------
__global__ void __launch_bounds__(128) mlp_kernel(
    const float* __restrict__ xyz,
    const float* __restrict__ w1, const float* __restrict__ b1,
    const float* __restrict__ w2, const float* __restrict__ b2,
    const float* __restrict__ w3, const float* __restrict__ b3,
    float* __restrict__ d_out)
{
    extern __shared__ float sm[];
    float4* sw1p = (float4*)sm;
    float*  sb2  = sm + 256;
    float*  sb3  = sm + 320;
    float*  sw2t = sm + 448;
    float*  sw3t = sm + 4544;
    float*  sout = sm + 12736;

    const int tid = threadIdx.x;
    if (tid < 64) {
        sw1p[tid] = make_float4(w1[tid * 67 + 0], w1[tid * 67 + 1], w1[tid * 67 + 2], b1[tid]);
        sb2[tid] = b2[tid];
    }
    if (tid < 128) sb3[tid] = b3[tid];
    for (int i = tid; i < 4096; i += 128) sw2t[i] = w2[(i & 63)  * 64 + (i >> 6)];
    for (int i = tid; i < 8192; i += 128) sw3t[i] = w3[(i & 127) * 64 + (i >> 7)];
    __syncthreads();

    const int wid = tid >> 5, lane = tid & 31;
    const int center0 = blockIdx.x * 4;
    const int center = center0 + wid;
    const int b = center >> 10;
    const int m0 = center0 & 1023;

    const float* newxyz = d_out;              // written by fps_kernel
    const float cx = newxyz[center * 3 + 0];
    const float cy = newxyz[center * 3 + 1];
    const float cz = newxyz[center * 3 + 2];

    const int ni = g_gidx[center * 32 + lane];
    const float* p = xyz + ((size_t)b * NPTS + ni) * 3;
    const float dx = p[0] - cx, dy = p[1] - cy, dz = p[2] - cz;

    // ---- layers 1+2 fused: h2 = relu(W2 @ relu(fp + Wxyz*d + b1) + b2) ----
    float h2[64];
#pragma unroll
    for (int o = 0; o < 64; ++o) h2[o] = sb2[o];

    const float4* fp4 = (const float4*)(g_featproj + ((size_t)b * NPTS + ni) * 64);
#pragma unroll 1
    for (int cc = 0; cc < 16; ++cc) {
        float4 f = fp4[cc];
        float fv[4] = {f.x, f.y, f.z, f.w};
#pragma unroll
        for (int j = 0; j < 4; ++j) {
            int c = cc * 4 + j;
            float4 wp = sw1p[c];
            float a = fmaf(wp.x, dx, fv[j]);
            a = fmaf(wp.y, dy, a);
            a = fmaf(wp.z, dz, a);
            a = fmaxf(a + wp.w, 0.0f);
            const float4* wrow = (const float4*)(sw2t + c * 64);
#pragma unroll
            for (int o4 = 0; o4 < 16; ++o4) {
                float4 w = wrow[o4];
                h2[o4 * 4 + 0] = fmaf(w.x, a, h2[o4 * 4 + 0]);
                h2[o4 * 4 + 1] = fmaf(w.y, a, h2[o4 * 4 + 1]);
                h2[o4 * 4 + 2] = fmaf(w.z, a, h2[o4 * 4 + 2]);
                h2[o4 * 4 + 3] = fmaf(w.w, a, h2[o4 * 4 + 3]);
            }
        }
    }
#pragma unroll
    for (int o = 0; o < 64; ++o) h2[o] = fmaxf(h2[o], 0.0f);

    // ---- layer 3 + warp max-pool ----
#pragma unroll 1
    for (int o4 = 0; o4 < 32; ++o4) {
        float4 bq = ((const float4*)sb3)[o4];
        float a0 = bq.x, a1 = bq.y, a2 = bq.z, a3 = bq.w;
#pragma unroll
        for (int c = 0; c < 64; ++c) {
            float4 w = ((const float4*)sw3t)[c * 32 + o4];
            a0 = fmaf(w.x, h2[c], a0);
            a1 = fmaf(w.y, h2[c], a1);
            a2 = fmaf(w.z, h2[c], a2);
            a3 = fmaf(w.w, h2[c], a3);
        }
        a0 = fmaxf(a0, 0.f); a1 = fmaxf(a1, 0.f);
        a2 = fmaxf(a2, 0.f); a3 = fmaxf(a3, 0.f);
#pragma unroll
        for (int s = 16; s > 0; s >>= 1) {
            a0 = fmaxf(a0, __shfl_xor_sync(0xffffffffu, a0, s));
            a1 = fmaxf(a1, __shfl_xor_sync(0xffffffffu, a1, s));
            a2 = fmaxf(a2, __shfl_xor_sync(0xffffffffu, a2, s));
            a3 = fmaxf(a3, __shfl_xor_sync(0xffffffffu, a3, s));
        }
        if (lane == 0) {
            sout[(o4 * 4 + 0) * 4 + wid] = a0;
            sout[(o4 * 4 + 1) * 4 + wid] = a1;
            sout[(o4 * 4 + 2) * 4 + wid] = a2;
            sout[(o4 * 4 + 3) * 4 + wid] = a3;
        }
    }
    __syncthreads();

    // coalesced float4 store: out[b][o][m0..m0+3]
    float* nf = d_out + BATCH * NPOINT_ * 3;
    const int o = tid;  // 0..127
    float4 v = *(float4*)&sout[o * 4];
    *(float4*)&nf[((size_t)b * 128 + o) * (size_t)NPOINT_ + m0] = v;
}

// ---------------------------------------------------------------------------
extern "C" void kernel_launch(void* const* d_in, const int* in_sizes, int n_in,
                              void* d_out, int out_size)
{
    const float* xyz      = (const float*)d_in[0];
    const float* features = (const float*)d_in[1];
    const float* w1 = (const float*)d_in[2];
    const float* b1 = (const float*)d_in[3];
    const float* w2 = (const float*)d_in[4];
    const float* b2 = (const float*)d_in[5];
    const float* w3 = (const float*)d_in[6];
    const float* b3 = (const float*)d_in[7];
    float* out = (float*)d_out;

    cudaFuncSetAttribute(mlp_kernel, cudaFuncAttributeMaxDynamicSharedMemorySize, 13248 * 4);

    featproj_kernel<<<8192, 256>>>(features, w1);
    fps_kernel<<<BATCH, 512>>>(xyz, out);
    ballquery_kernel<<<1024, 256>>>(xyz, out);
    mlp_kernel<<<2048, 128, 13248 * 4>>>(xyz, w1, b1, w2, b2, w3, b3, out);
}

// round 3
// speedup vs baseline: 1.0849x; 1.0849x over previous
#include <cuda_runtime.h>
#include <cuda_bf16.h>
#include <cstdint>
#include <cstddef>

#define BATCH    8
#define NPTS     8192
#define NPOINT_  1024
#define NSAMPLE_ 32
#define CFEAT    64

// scratch (device globals; no allocation allowed)
__device__ int   g_gidx[BATCH * NPOINT_ * NSAMPLE_];   // ball-query neighbor indices
__device__ float g_featproj[BATCH * NPTS * CFEAT];     // W1[:,3:] @ features per unique point

// ---------------- f32x2 helpers (Blackwell packed fp32; IEEE per lane) ------
__device__ __forceinline__ unsigned long long f2_pack(float a, float b) {
    unsigned long long r;
    asm("mov.b64 %0, {%1, %2};" : "=l"(r) : "r"(__float_as_uint(a)), "r"(__float_as_uint(b)));
    return r;
}
__device__ __forceinline__ unsigned long long f2_bcast(float a) {
    unsigned long long r;
    unsigned x = __float_as_uint(a);
    asm("mov.b64 %0, {%1, %1};" : "=l"(r) : "r"(x));
    return r;
}
__device__ __forceinline__ void f2_unpack(unsigned long long v, float& lo, float& hi) {
    unsigned a, b;
    asm("mov.b64 {%0, %1}, %2;" : "=r"(a), "=r"(b) : "l"(v));
    lo = __uint_as_float(a); hi = __uint_as_float(b);
}
__device__ __forceinline__ unsigned long long f2_add(unsigned long long a, unsigned long long b) {
    unsigned long long d;
    asm("add.rn.f32x2 %0, %1, %2;" : "=l"(d) : "l"(a), "l"(b));
    return d;
}
__device__ __forceinline__ unsigned long long f2_mul(unsigned long long a, unsigned long long b) {
    unsigned long long d;
    asm("mul.rn.f32x2 %0, %1, %2;" : "=l"(d) : "l"(a), "l"(b));
    return d;
}
__device__ __forceinline__ unsigned long long f2_fma(unsigned long long a, unsigned long long b,
                                                     unsigned long long c) {
    unsigned long long d;
    asm("fma.rn.f32x2 %0, %1, %2, %3;" : "=l"(d) : "l"(a), "l"(b), "l"(c));
    return d;
}

// ---------------------------------------------------------------------------
// Kernel 1: farthest point sampling. One CTA/batch, 512 thr x 16 pts (8 f32x2
// pairs) in registers. xyz cached in 96KB dynamic smem for winner lookup.
// Parallel argmax: fmax tree + equality mask + REDUX two-phase reduction.
// Distance arithmetic is bitwise-identical to the previously passing version.
// ---------------------------------------------------------------------------
__global__ void __launch_bounds__(512, 1) fps_kernel(const float* __restrict__ xyz,
                                                     float* __restrict__ newxyz)
{
    extern __shared__ float fsm[];
    float* sx = fsm;
    float* sy = fsm + NPTS;
    float* sz = fsm + 2 * NPTS;
    __shared__ unsigned swd[2][16];
    __shared__ unsigned swi[2][16];

    const int b = blockIdx.x;
    const int t = threadIdx.x;
    const float* xb = xyz + (size_t)b * NPTS * 3;

    unsigned long long px2[8], py2[8], pz2[8];
    float pd[16];
#pragma unroll
    for (int q = 0; q < 8; ++q) {
        int i0 = t + (2 * q) * 512;
        int i1 = t + (2 * q + 1) * 512;
        float x0 = xb[i0 * 3 + 0], y0 = xb[i0 * 3 + 1], z0 = xb[i0 * 3 + 2];
        float x1 = xb[i1 * 3 + 0], y1 = xb[i1 * 3 + 1], z1 = xb[i1 * 3 + 2];
        px2[q] = f2_pack(x0, x1);
        py2[q] = f2_pack(y0, y1);
        pz2[q] = f2_pack(z0, z1);
        pd[2 * q] = 1e10f; pd[2 * q + 1] = 1e10f;
        sx[i0] = x0; sy[i0] = y0; sz[i0] = z0;
        sx[i1] = x1; sy[i1] = y1; sz[i1] = z1;
    }
    __syncthreads();

    float lx = sx[0], ly = sy[0], lz = sz[0];
    if (t == 0) {
        newxyz[b * NPOINT_ * 3 + 0] = lx;
        newxyz[b * NPOINT_ * 3 + 1] = ly;
        newxyz[b * NPOINT_ * 3 + 2] = lz;
    }
    const int lane = t & 31, wid = t >> 5;

    for (int it = 1; it < NPOINT_; ++it) {
        const unsigned long long nlx = f2_bcast(-lx);
        const unsigned long long nly = f2_bcast(-ly);
        const unsigned long long nlz = f2_bcast(-lz);
#pragma unroll
        for (int q = 0; q < 8; ++q) {
            unsigned long long dx = f2_add(px2[q], nlx);
            unsigned long long dy = f2_add(py2[q], nly);
            unsigned long long dz = f2_add(pz2[q], nlz);
            // d = fma(dx,dx, fma(dy,dy, dz*dz))  -- same order as passing kernel
            unsigned long long d2 = f2_fma(dx, dx, f2_fma(dy, dy, f2_mul(dz, dz)));
            float d0, d1;
            f2_unpack(d2, d0, d1);
            pd[2 * q]     = fminf(pd[2 * q],     d0);
            pd[2 * q + 1] = fminf(pd[2 * q + 1], d1);
        }
        // parallel max tree over 16 distances
        float m0 = fmaxf(pd[0], pd[1]),  m1 = fmaxf(pd[2], pd[3]);
        float m2 = fmaxf(pd[4], pd[5]),  m3 = fmaxf(pd[6], pd[7]);
        float m4 = fmaxf(pd[8], pd[9]),  m5 = fmaxf(pd[10], pd[11]);
        float m6 = fmaxf(pd[12], pd[13]), m7 = fmaxf(pd[14], pd[15]);
        m0 = fmaxf(m0, m1); m2 = fmaxf(m2, m3); m4 = fmaxf(m4, m5); m6 = fmaxf(m6, m7);
        m0 = fmaxf(m0, m2); m4 = fmaxf(m4, m6);
        const float vmax = fmaxf(m0, m4);
        // smallest j with pd[j]==vmax (first-occurrence semantics)
        unsigned msk = 0;
#pragma unroll
        for (int j = 0; j < 16; ++j) msk |= (pd[j] == vmax) ? (1u << j) : 0u;
        const int bj = __ffs(msk) - 1;
        const unsigned gidx = (unsigned)(t + bj * 512);

        // warp reduce: max dist bits (nonneg floats -> monotone), then min index
        const unsigned vb = __float_as_uint(vmax);
        const unsigned wm = __reduce_max_sync(0xffffffffu, vb);
        const unsigned cand = (vb == wm) ? gidx : 0xffffffffu;
        const unsigned wi = __reduce_min_sync(0xffffffffu, cand);

        const int buf = it & 1;
        if (lane == 0) { swd[buf][wid] = wm; swi[buf][wid] = wi; }
        __syncthreads();

        // CTA reduce, redundantly in every warp (no broadcast barrier needed)
        const unsigned pdw = swd[buf][lane & 15];
        const unsigned piw = swi[buf][lane & 15];
        const unsigned cm = __reduce_max_sync(0xffffffffu, pdw);
        const unsigned c2 = (pdw == cm) ? piw : 0xffffffffu;
        const unsigned win = __reduce_min_sync(0xffffffffu, c2);

        lx = sx[win]; ly = sy[win]; lz = sz[win];
        if (t == 0) {
            newxyz[(b * NPOINT_ + it) * 3 + 0] = lx;
            newxyz[(b * NPOINT_ + it) * 3 + 1] = ly;
            newxyz[(b * NPOINT_ + it) * 3 + 2] = lz;
        }
    }
}

// ---------------------------------------------------------------------------
// Kernel 2: layer-1 feature projection for all unique points.
// ---------------------------------------------------------------------------
__global__ void __launch_bounds__(256) featproj_kernel(const float* __restrict__ feat,
                                                       const float* __restrict__ w1)
{
    __shared__ float ws[64 * 65];
    __shared__ float sf[8][64];

    const int tid = threadIdx.x;
    for (int i = tid; i < 64 * 64; i += 256) {
        int o = i >> 6, c = i & 63;
        ws[o * 65 + c] = w1[o * 67 + 3 + c];
    }
    __syncthreads();

    const int wid = tid >> 5, lane = tid & 31;
    const int row = blockIdx.x * 8 + wid;
    const float* fr = feat + (size_t)row * 64;
    sf[wid][lane]      = fr[lane];
    sf[wid][lane + 32] = fr[lane + 32];
    __syncwarp();

    float a0 = 0.f, a1 = 0.f;
#pragma unroll
    for (int c = 0; c < 64; ++c) {
        float f = sf[wid][c];
        a0 = fmaf(ws[lane * 65 + c],        f, a0);
        a1 = fmaf(ws[(lane + 32) * 65 + c], f, a1);
    }
    float* outr = g_featproj + (size_t)row * 64;
    outr[lane]      = a0;
    outr[lane + 32] = a1;
}

// ---------------------------------------------------------------------------
// Kernel 3: ball query. One warp per center; first-32-by-index, pad with first.
// ---------------------------------------------------------------------------
__global__ void __launch_bounds__(256) ballquery_kernel(const float* __restrict__ xyz,
                                                        const float* __restrict__ newxyz)
{
    const int gw = (blockIdx.x * blockDim.x + threadIdx.x) >> 5;
    const int lane = threadIdx.x & 31;
    const int b = gw >> 10;
    const float* xb = xyz + (size_t)b * NPTS * 3;
    const float cx = newxyz[gw * 3 + 0];
    const float cy = newxyz[gw * 3 + 1];
    const float cz = newxyz[gw * 3 + 2];
    int* out = g_gidx + gw * 32;

    const float R2 = (float)(0.4 * 0.4);
    int cnt = 0, first = 0;
    bool hasfirst = false;
    for (int p0 = 0; p0 < NPTS && cnt < 32; p0 += 32) {
        int p = p0 + lane;
        float dx = xb[p * 3 + 0] - cx;
        float dy = xb[p * 3 + 1] - cy;
        float dz = xb[p * 3 + 2] - cz;
        float d2 = fmaf(dx, dx, fmaf(dy, dy, dz * dz));
        bool in = d2 < R2;
        unsigned mask = __ballot_sync(0xffffffffu, in);
        if (mask) {
            if (!hasfirst) { first = p0 + __ffs(mask) - 1; hasfirst = true; }
            int ofs = cnt + __popc(mask & ((1u << lane) - 1u));
            if (in && ofs < 32) out[ofs] = p;
            cnt += __popc(mask);
        }
    }
    for (int s = cnt + lane; s < 32; s += 32) out[s] = first;
}

// ---------------------------------------------------------------------------
// Kernel 4: fused gather + 3-layer MLP + max-pool. Warp per center, lane = sample.
// ---------------------------------------------------------------------------
__global__ void __launch_bounds__(128) mlp_kernel(
    const float* __restrict__ xyz,
    const float* __restrict__ w1, const float* __restrict__ b1,
    const float* __restrict__ w2, const float* __restrict__ b2,
    const float* __restrict__ w3, const float* __restrict__ b3,
    float* __restrict__ d_out)
{
    extern __shared__ float sm[];
    float4* sw1p = (float4*)sm;
    float*  sb2  = sm + 256;
    float*  sb3  = sm + 320;
    float*  sw2t = sm + 448;
    float*  sw3t = sm + 4544;
    float*  sout = sm + 12736;

    const int tid = threadIdx.x;
    const int wid = tid >> 5, lane = tid & 31;
    const int center0 = blockIdx.x * 4;
    const int center = center0 + wid;
    const int b = center >> 10;
    const int m0 = center0 & 1023;

    // gather index + prefetch the 256B featproj row into L1 before weight fill
    const int ni = g_gidx[center * 32 + lane];
    const float* fpr = g_featproj + ((size_t)b * NPTS + ni) * 64;
    asm volatile("prefetch.global.L1 [%0];"      :: "l"(fpr));
    asm volatile("prefetch.global.L1 [%0+128];"  :: "l"(fpr));
    const float* p = xyz + ((size_t)b * NPTS + ni) * 3;
    asm volatile("prefetch.global.L1 [%0];"      :: "l"(p));

    if (tid < 64) {
        sw1p[tid] = make_float4(w1[tid * 67 + 0], w1[tid * 67 + 1], w1[tid * 67 + 2], b1[tid]);
        sb2[tid] = b2[tid];
    }
    if (tid < 128) sb3[tid] = b3[tid];
    for (int i = tid; i < 4096; i += 128) sw2t[i] = w2[(i & 63)  * 64 + (i >> 6)];
    for (int i = tid; i < 8192; i += 128) sw3t[i] = w3[(i & 127) * 64 + (i >> 7)];
    __syncthreads();

    const float* newxyz = d_out;              // written by fps_kernel
    const float cx = newxyz[center * 3 + 0];
    const float cy = newxyz[center * 3 + 1];
    const float cz = newxyz[center * 3 + 2];
    const float dx = p[0] - cx, dy = p[1] - cy, dz = p[2] - cz;

    // ---- layers 1+2 fused ----
    float h2[64];
#pragma unroll
    for (int o = 0; o < 64; ++o) h2[o] = sb2[o];

    const float4* fp4 = (const float4*)fpr;
    float4 fnext = fp4[0];
#pragma unroll 1
    for (int cc = 0; cc < 16; ++cc) {
        float4 f = fnext;
        if (cc < 15) fnext = fp4[cc + 1];   // 1-deep software pipeline
        float fv[4] = {f.x, f.y, f.z, f.w};
#pragma unroll
        for (int j = 0; j < 4; ++j) {
            int c = cc * 4 + j;
            float4 wp = sw1p[c];
            float a = fmaf(wp.x, dx, fv[j]);
            a = fmaf(wp.y, dy, a);
            a = fmaf(wp.z, dz, a);
            a = fmaxf(a + wp.w, 0.0f);
            const float4* wrow = (const float4*)(sw2t + c * 64);
#pragma unroll
            for (int o4 = 0; o4 < 16; ++o4) {
                float4 w = wrow[o4];
                h2[o4 * 4 + 0] = fmaf(w.x, a, h2[o4 * 4 + 0]);
                h2[o4 * 4 + 1] = fmaf(w.y, a, h2[o4 * 4 + 1]);
                h2[o4 * 4 + 2] = fmaf(w.z, a, h2[o4 * 4 + 2]);
                h2[o4 * 4 + 3] = fmaf(w.w, a, h2[o4 * 4 + 3]);
            }
        }
    }
#pragma unroll
    for (int o = 0; o < 64; ++o) h2[o] = fmaxf(h2[o], 0.0f);

    // ---- layer 3 + warp max-pool ----
#pragma unroll 1
    for (int o4 = 0; o4 < 32; ++o4) {
        float4 bq = ((const float4*)sb3)[o4];
        float a0 = bq.x, a1 = bq.y, a2 = bq.z, a3 = bq.w;
#pragma unroll
        for (int c = 0; c < 64; ++c) {
            float4 w = ((const float4*)sw3t)[c * 32 + o4];
            a0 = fmaf(w.x, h2[c], a0);
            a1 = fmaf(w.y, h2[c], a1);
            a2 = fmaf(w.z, h2[c], a2);
            a3 = fmaf(w.w, h2[c], a3);
        }
        a0 = fmaxf(a0, 0.f); a1 = fmaxf(a1, 0.f);
        a2 = fmaxf(a2, 0.f); a3 = fmaxf(a3, 0.f);
#pragma unroll
        for (int s = 16; s > 0; s >>= 1) {
            a0 = fmaxf(a0, __shfl_xor_sync(0xffffffffu, a0, s));
            a1 = fmaxf(a1, __shfl_xor_sync(0xffffffffu, a1, s));
            a2 = fmaxf(a2, __shfl_xor_sync(0xffffffffu, a2, s));
            a3 = fmaxf(a3, __shfl_xor_sync(0xffffffffu, a3, s));
        }
        if (lane == 0) {
            sout[(o4 * 4 + 0) * 4 + wid] = a0;
            sout[(o4 * 4 + 1) * 4 + wid] = a1;
            sout[(o4 * 4 + 2) * 4 + wid] = a2;
            sout[(o4 * 4 + 3) * 4 + wid] = a3;
        }
    }
    __syncthreads();

    float* nf = d_out + BATCH * NPOINT_ * 3;
    const int o = tid;
    float4 v = *(float4*)&sout[o * 4];
    *(float4*)&nf[((size_t)b * 128 + o) * (size_t)NPOINT_ + m0] = v;
}

// ---------------------------------------------------------------------------
extern "C" void kernel_launch(void* const* d_in, const int* in_sizes, int n_in,
                              void* d_out, int out_size)
{
    const float* xyz      = (const float*)d_in[0];
    const float* features = (const float*)d_in[1];
    const float* w1 = (const float*)d_in[2];
    const float* b1 = (const float*)d_in[3];
    const float* w2 = (const float*)d_in[4];
    const float* b2 = (const float*)d_in[5];
    const float* w3 = (const float*)d_in[6];
    const float* b3 = (const float*)d_in[7];
    float* out = (float*)d_out;

    cudaFuncSetAttribute(fps_kernel, cudaFuncAttributeMaxDynamicSharedMemorySize, NPTS * 3 * 4);
    cudaFuncSetAttribute(mlp_kernel, cudaFuncAttributeMaxDynamicSharedMemorySize, 13248 * 4);

    featproj_kernel<<<8192, 256>>>(features, w1);
    fps_kernel<<<BATCH, 512, NPTS * 3 * 4>>>(xyz, out);
    ballquery_kernel<<<1024, 256>>>(xyz, out);
    mlp_kernel<<<2048, 128, 13248 * 4>>>(xyz, w1, b1, w2, b2, w3, b3, out);
}